// round 8
// baseline (speedup 1.0000x reference)
#include <cuda_runtime.h>
#include <mma.h>
#include <type_traits>
#include <cstdint>

using namespace nvcuda;

#define N_B   64
#define P_P   64
#define ENC_C 1536
#define T_T   32
#define V_V   10000
#define E_E   512
#define A_A   512
#define H_H   512
#define XDIM  2560   // ENC + E + H
#define GDIM  2048   // 4*H
#define PENC  98304  // P * ENC
#define HOFF  (ENC_C + E_E)   // 2048, offset of h inside xcat
#define NBLK  128

// ---------------- device scratch (module globals: allocation-free) ----------
__device__ float g_attn_img[N_B * P_P * A_A];   // 8 MB
__device__ float g_emb[T_T * N_B * E_E];        // 4 MB
__device__ float g_hall[T_T * N_B * H_H];       // 4 MB
__device__ float g_Wcat[GDIM * XDIM];           // 20 MB [W_ih | W_hh], tf32-rounded
__device__ float g_bcat[GDIM];
__device__ float g_xcat[N_B * XDIM];            // [ctx | emb | h]
__device__ float g_gpart[4 * N_B * GDIM];       // split-K partials (deterministic)
__device__ float g_cstate[N_B * H_H];
__device__ float g_attn_h[N_B * A_A];

// ---------------- flag-array grid barrier (parallel arrivals) ---------------
__device__ unsigned g_flags[NBLK];   // block b's arrival epoch (monotonic)
__device__ unsigned g_rel;           // released epoch (monotonic across replays)

__device__ __forceinline__ void gsync(unsigned ep) {
    __syncthreads();
    __threadfence();
    const int b = blockIdx.x, tid = threadIdx.x;
    if (b == 0) {
        if (tid > 0 && tid < NBLK) {
            while (*(volatile unsigned*)&g_flags[tid] < ep) { }
        }
        __syncthreads();
        if (tid == 0) { __threadfence(); *(volatile unsigned*)&g_rel = ep; }
    } else {
        if (tid == 0) {
            *(volatile unsigned*)&g_flags[b] = ep;
            while (*(volatile unsigned*)&g_rel < ep) { }
        }
    }
    __syncthreads();
    __threadfence();
}

__device__ __forceinline__ float tf32r(float x) { return wmma::__float_to_tf32(x); }

// ---------------- MT x 128 tile tf32 GEMM (A @ B^T + bias) ------------------
// A (M,K) row-major, B (N,K) row-major. tf32 rounding at smem store.
// MODE 0: C[gm*ldc+gn] = v + bias. MODE 2: fc remap row (gm&63)*T+(gm>>6).
template<int MT, int MODE>
__global__ void __launch_bounds__(256, 2) gemm_big(
    const float* __restrict__ A, int lda,
    const float* __restrict__ B, int ldb,
    const float* __restrict__ bias,
    float* __restrict__ C, int ldc,
    int N, int K)
{
    constexpr int AI = MT / 32;            // float4 A-loads per thread per chunk
    constexpr int WM = MT / 64;            // m-fragments per warp
    __shared__ float sh[(MT + 128) * 36];
    float* As = sh;
    float* Bs = sh + MT * 36;

    const int m0   = blockIdx.y * MT;
    const int n0   = blockIdx.x * 128;
    const int tid  = threadIdx.x;
    const int warp = tid >> 5;
    const int wm   = (warp & 3) * (MT / 4);
    const int wn   = (warp >> 2) << 6;     // 0,64

    wmma::fragment<wmma::accumulator, 16, 16, 8, float> acc[WM][4];
    #pragma unroll
    for (int i = 0; i < WM; i++)
        #pragma unroll
        for (int j = 0; j < 4; j++) wmma::fill_fragment(acc[i][j], 0.0f);

    float4 ra[AI], rb[4];

    #pragma unroll
    for (int i = 0; i < AI; i++) {
        int idx = tid + i * 256, m = idx >> 3, k4 = (idx & 7) << 2;
        ra[i] = *(const float4*)(A + (size_t)(m0 + m) * lda + k4);
    }
    #pragma unroll
    for (int i = 0; i < 4; i++) {
        int idx = tid + i * 256, m = idx >> 3, k4 = (idx & 7) << 2;
        int gn = n0 + m;
        rb[i] = (gn < N) ? *(const float4*)(B + (size_t)gn * ldb + k4)
                         : make_float4(0.f, 0.f, 0.f, 0.f);
    }

    for (int ko = 0; ko < K; ko += 32) {
        #pragma unroll
        for (int i = 0; i < AI; i++) {
            int idx = tid + i * 256, m = idx >> 3, k4 = (idx & 7) << 2;
            float* pa = As + m * 36 + k4;
            pa[0] = tf32r(ra[i].x); pa[1] = tf32r(ra[i].y);
            pa[2] = tf32r(ra[i].z); pa[3] = tf32r(ra[i].w);
        }
        #pragma unroll
        for (int i = 0; i < 4; i++) {
            int idx = tid + i * 256, m = idx >> 3, k4 = (idx & 7) << 2;
            float* pb = Bs + m * 36 + k4;
            pb[0] = tf32r(rb[i].x); pb[1] = tf32r(rb[i].y);
            pb[2] = tf32r(rb[i].z); pb[3] = tf32r(rb[i].w);
        }
        __syncthreads();

        const int kn = ko + 32;
        if (kn < K) {
            #pragma unroll
            for (int i = 0; i < AI; i++) {
                int idx = tid + i * 256, m = idx >> 3, k4 = (idx & 7) << 2;
                ra[i] = *(const float4*)(A + (size_t)(m0 + m) * lda + kn + k4);
            }
            #pragma unroll
            for (int i = 0; i < 4; i++) {
                int idx = tid + i * 256, m = idx >> 3, k4 = (idx & 7) << 2;
                int gn = n0 + m;
                rb[i] = (gn < N) ? *(const float4*)(B + (size_t)gn * ldb + kn + k4)
                                 : make_float4(0.f, 0.f, 0.f, 0.f);
            }
        }

        #pragma unroll
        for (int kk = 0; kk < 32; kk += 8) {
            wmma::fragment<wmma::matrix_a, 16, 16, 8, wmma::precision::tf32, wmma::row_major> af[WM];
            wmma::fragment<wmma::matrix_b, 16, 16, 8, wmma::precision::tf32, wmma::col_major> bf[4];
            #pragma unroll
            for (int i = 0; i < WM; i++)
                wmma::load_matrix_sync(af[i], As + (wm + i * 16) * 36 + kk, 36);
            #pragma unroll
            for (int j = 0; j < 4; j++)
                wmma::load_matrix_sync(bf[j], Bs + (wn + j * 16) * 36 + kk, 36);
            #pragma unroll
            for (int i = 0; i < WM; i++)
                #pragma unroll
                for (int j = 0; j < 4; j++)
                    wmma::mma_sync(acc[i][j], af[i], bf[j], acc[i][j]);
        }
        __syncthreads();
    }

    // epilogue: two N-half waves staged through smem [MT][68]
    #pragma unroll
    for (int wave = 0; wave < 2; wave++) {
        if ((warp >> 2) == wave) {
            #pragma unroll
            for (int i = 0; i < WM; i++)
                #pragma unroll
                for (int j = 0; j < 4; j++)
                    wmma::store_matrix_sync(sh + (wm + i * 16) * 68 + j * 16,
                                            acc[i][j], 68, wmma::mem_row_major);
        }
        __syncthreads();
        for (int idx = tid; idx < MT * 64; idx += 256) {
            int m = idx >> 6, nn = idx & 63;
            int gm = m0 + m, gn = n0 + wave * 64 + nn;
            if (gn >= N) continue;
            float v = sh[m * 68 + nn] + bias[gn];
            if (MODE == 0) {
                C[(size_t)gm * ldc + gn] = v;
            } else {
                int row = (gm & 63) * T_T + (gm >> 6);
                C[(size_t)row * ldc + gn] = v;
            }
        }
        __syncthreads();
    }
}

// ---------------- init GEMM: 64(M) x 128(N) tile, split-K atomic ------------
__global__ void __launch_bounds__(256, 2) gemm_init(
    const float* __restrict__ A, int lda,
    const float* __restrict__ B, const float* __restrict__ B2, int ldb,
    float* __restrict__ C, int ldc,
    float* __restrict__ C2, int ldc2,
    int K, int kChunk)
{
    __shared__ float sh[64 * 132];
    float* As = sh;                          // [64][36]
    float* Bs = sh + 64 * 36;                // [32][132]

    const int n0   = blockIdx.x * 128;
    const int kBeg = blockIdx.z * kChunk;
    const int kEnd = min(K, kBeg + kChunk);
    const int tid  = threadIdx.x;
    const int warp = tid >> 5;

    const float* Bp = B;
    int nB0 = n0;
    if (n0 >= 512) { Bp = B2; nB0 = n0 - 512; }

    wmma::fragment<wmma::accumulator, 16, 16, 8, float> acc[4];
    #pragma unroll
    for (int i = 0; i < 4; i++) wmma::fill_fragment(acc[i], 0.0f);

    float4 ra[2], rb[4];
    {
        const int ko = kBeg;
        #pragma unroll
        for (int i = 0; i < 2; i++) {
            int idx = tid + i * 256, m = idx >> 3, k4 = (idx & 7) << 2;
            ra[i] = *(const float4*)(A + (size_t)m * lda + ko + k4);
        }
        #pragma unroll
        for (int i = 0; i < 4; i++) {
            int idx = tid + i * 256, k = idx >> 5, n4 = (idx & 31) << 2;
            rb[i] = *(const float4*)(Bp + (size_t)(ko + k) * ldb + nB0 + n4);
        }
    }

    for (int ko = kBeg; ko < kEnd; ko += 32) {
        #pragma unroll
        for (int i = 0; i < 2; i++) {
            int idx = tid + i * 256, m = idx >> 3, k4 = (idx & 7) << 2;
            float* pa = As + m * 36 + k4;
            pa[0] = tf32r(ra[i].x); pa[1] = tf32r(ra[i].y);
            pa[2] = tf32r(ra[i].z); pa[3] = tf32r(ra[i].w);
        }
        #pragma unroll
        for (int i = 0; i < 4; i++) {
            int idx = tid + i * 256, k = idx >> 5, n4 = (idx & 31) << 2;
            float* pb = Bs + k * 132 + n4;
            pb[0] = tf32r(rb[i].x); pb[1] = tf32r(rb[i].y);
            pb[2] = tf32r(rb[i].z); pb[3] = tf32r(rb[i].w);
        }
        __syncthreads();

        const int kn = ko + 32;
        if (kn < kEnd) {
            #pragma unroll
            for (int i = 0; i < 2; i++) {
                int idx = tid + i * 256, m = idx >> 3, k4 = (idx & 7) << 2;
                ra[i] = *(const float4*)(A + (size_t)m * lda + kn + k4);
            }
            #pragma unroll
            for (int i = 0; i < 4; i++) {
                int idx = tid + i * 256, k = idx >> 5, n4 = (idx & 31) << 2;
                rb[i] = *(const float4*)(Bp + (size_t)(kn + k) * ldb + nB0 + n4);
            }
        }

        #pragma unroll
        for (int kk = 0; kk < 32; kk += 8) {
            wmma::fragment<wmma::matrix_b, 16, 16, 8, wmma::precision::tf32, wmma::row_major> bf;
            wmma::load_matrix_sync(bf, Bs + kk * 132 + warp * 16, 132);
            #pragma unroll
            for (int i = 0; i < 4; i++) {
                wmma::fragment<wmma::matrix_a, 16, 16, 8, wmma::precision::tf32, wmma::row_major> af;
                wmma::load_matrix_sync(af, As + (i * 16) * 36 + kk, 36);
                wmma::mma_sync(acc[i], af, bf, acc[i]);
            }
        }
        __syncthreads();
    }

    #pragma unroll
    for (int i = 0; i < 4; i++)
        wmma::store_matrix_sync(sh + (i * 16) * 132 + warp * 16, acc[i], 132, wmma::mem_row_major);
    __syncthreads();

    for (int idx = tid; idx < 64 * 128; idx += 256) {
        int m = idx >> 7, n = idx & 127;
        int gn = n0 + n;
        float v = sh[m * 132 + n];
        if (gn < 512) atomicAdd(&C[(size_t)m * ldc + gn], v);
        else          atomicAdd(&C2[(size_t)m * ldc2 + gn - 512], v);
    }
}

// ---------------- prologue: embedding gather + state zero -------------------
__global__ void prep_kernel(const float* __restrict__ embW,
                            const int*   __restrict__ captions)
{
    int b = blockIdx.x;           // (t, n)
    int t = b >> 6, n = b & 63;
    int e = threadIdx.x;          // 512
    int cap = captions[n * T_T + t];
    float v = embW[(size_t)cap * E_E + e];
    g_emb[((size_t)t * N_B + n) * E_E + e] = v;
    if (t == 0) {
        g_xcat[n * XDIM + ENC_C + e]       = v;     // emb slot, step 0
        g_xcat[n * XDIM + HOFF + e]        = 0.0f;  // h slot (init gemm adds)
        g_cstate[n * H_H + e]              = 0.0f;  // c (init gemm adds)
    }
}

// ---------------- prologue: concat LSTM weights (tf32-rounded) --------------
__global__ void wcat_kernel(const float* __restrict__ Wih, const float* __restrict__ bih,
                            const float* __restrict__ Whh, const float* __restrict__ bhh)
{
    int idx = blockIdx.x * 1024 + threadIdx.x;
    if (idx < GDIM * XDIM) {
        int j = idx / XDIM, k = idx % XDIM;
        float v = (k < HOFF) ? Wih[j * HOFF + k] : Whh[j * H_H + (k - HOFF)];
        g_Wcat[idx] = tf32r(v);
    }
    if (idx < GDIM) g_bcat[idx] = bih[idx] + bhh[idx];
}

// ---------------- persistent decode loop ------------------------------------
// dynamic smem layout (floats):
//   w_res  [64][652]   0      .. 41728   (this block's Wcat slice, resident)
//   As     [2][64][68] 41728  .. 50432   (xcat stage; also P3 epilogue)
//   s_tok  [4][512]    50432  .. 52480
//   s_w    [512]       52480  .. 52992
//   s_ah   [512]       52992  .. 53504
//   s_sc   [64]        53504  .. 53568
#define DSM_FLOATS 53568

__global__ void __launch_bounds__(256) decode_loop(
    const float* __restrict__ features,
    const float* __restrict__ tokW, const float* __restrict__ tokb,
    const float* __restrict__ fullW, const float* __restrict__ fullb)
{
    extern __shared__ float dsm[];
    float* w_res = dsm;
    float* As    = dsm + 41728;
    float* s_tok = dsm + 50432;
    float* s_w   = dsm + 52480;
    float* s_ah  = dsm + 52992;
    float* s_sc  = dsm + 53504;

    const int b    = blockIdx.x;
    const int tid  = threadIdx.x;
    const int warp = tid >> 5;
    const int lane = tid & 31;

    // epoch base (monotonic across graph replays; stable until first release)
    unsigned ep = *(volatile unsigned*)&g_rel;

    // persistent cell state: this thread owns element (en, ej)
    const int eidx = b * 256 + tid;
    const int en = eidx >> 9, ej = eidx & 511;
    float creg = g_cstate[en * H_H + ej];

    // P3 assignment
    const int nt = b >> 2, kz = b & 3;
    const int n0 = nt * 64, kb = kz * 640;
    const int m16 = (warp >> 1) * 16;
    const int nb2 = (warp & 1) * 32;

    // resident Wcat slice: 64 rows x 640 K (tf32 pre-rounded)
    for (int i = tid; i < 64 * 160; i += 256) {
        int n = i / 160, k4 = (i % 160) << 2;
        *(float4*)(w_res + n * 652 + k4) =
            *(const float4*)(g_Wcat + (size_t)(n0 + n) * XDIM + kb + k4);
    }

    // step-invariant smem: tokW rows [4b, 4b+4) and fullW
    const int c0 = b * 4;
    #pragma unroll
    for (int i = 0; i < 2; i++) {
        int idx = tid + i * 256, c = idx >> 7, k4 = (idx & 127) << 2;
        *(float4*)(s_tok + c * 512 + k4) =
            *(const float4*)(tokW + (size_t)(c0 + c) * H_H + k4);
    }
    for (int a = tid; a < A_A; a += 256) s_w[a] = fullW[a];
    const int pq = tid & 3;
    const float tb = tokb[c0 + pq];
    const float fb = fullb[0];
    __syncthreads();

    for (int t = 0; t < T_T; t++) {
        // ===== P1: attn_h = h @ tokW^T + tokb (cols c0..c0+3, all n) ========
        {
            const int n = tid >> 2;                 // 0..63
            const float* hb = g_xcat + (size_t)n * XDIM + HOFF + pq * 128;
            float a0 = 0.f, a1 = 0.f, a2 = 0.f, a3 = 0.f;
            #pragma unroll 4
            for (int j = 0; j < 128; j += 4) {
                float4 hv = __ldcg((const float4*)(hb + j));
                const float* w0 = s_tok + pq * 128 + j;
                a0 += hv.x * w0[0]    + hv.y * w0[1]    + hv.z * w0[2]    + hv.w * w0[3];
                a1 += hv.x * w0[512]  + hv.y * w0[513]  + hv.z * w0[514]  + hv.w * w0[515];
                a2 += hv.x * w0[1024] + hv.y * w0[1025] + hv.z * w0[1026] + hv.w * w0[1027];
                a3 += hv.x * w0[1536] + hv.y * w0[1537] + hv.z * w0[1538] + hv.w * w0[1539];
            }
            #pragma unroll
            for (int off = 1; off < 4; off <<= 1) {
                a0 += __shfl_xor_sync(0xffffffffu, a0, off);
                a1 += __shfl_xor_sync(0xffffffffu, a1, off);
                a2 += __shfl_xor_sync(0xffffffffu, a2, off);
                a3 += __shfl_xor_sync(0xffffffffu, a3, off);
            }
            float r = (pq == 0) ? a0 : (pq == 1) ? a1 : (pq == 2) ? a2 : a3;
            g_attn_h[n * A_A + c0 + pq] = r + tb;
        }
        gsync(++ep);

        // ===== P2: attention scores + softmax + ctx (block pair per n) ======
        {
            const int n = b >> 1, half = b & 1;
            for (int a = tid; a < A_A; a += 256)
                s_ah[a] = __ldcg(g_attn_h + n * A_A + a);
            __syncthreads();

            const float* aim = g_attn_img + (size_t)n * P_P * A_A;
            for (int p = warp; p < P_P; p += 8) {
                float s = 0.0f;
                const float* row = aim + p * A_A;
                #pragma unroll 4
                for (int a = lane; a < A_A; a += 32) {
                    float e = s_ah[a] + row[a];
                    if (e > 0.0f) s += e * s_w[a];
                }
                #pragma unroll
                for (int o = 16; o > 0; o >>= 1) s += __shfl_xor_sync(0xffffffffu, s, o);
                if (lane == 0) s_sc[p] = s + fb;
            }
            __syncthreads();

            if (warp == 0) {
                float v0 = s_sc[lane], v1 = s_sc[lane + 32];
                float mx = fmaxf(v0, v1);
                #pragma unroll
                for (int o = 16; o > 0; o >>= 1) mx = fmaxf(mx, __shfl_xor_sync(0xffffffffu, mx, o));
                float e0 = __expf(v0 - mx), e1 = __expf(v1 - mx);
                float sm = e0 + e1;
                #pragma unroll
                for (int o = 16; o > 0; o >>= 1) sm += __shfl_xor_sync(0xffffffffu, sm, o);
                float inv = 1.0f / sm;
                s_sc[lane]      = e0 * inv;
                s_sc[lane + 32] = e1 * inv;
            }
            __syncthreads();

            const float* fn  = features + (size_t)n * P_P * ENC_C;
            float*       ctx = g_xcat + n * XDIM;
            for (int c = half * 768 + tid; c < half * 768 + 768; c += 256) {
                float a0 = 0.0f;
                #pragma unroll 8
                for (int p = 0; p < P_P; p++) a0 += s_sc[p] * fn[(size_t)p * ENC_C + c];
                ctx[c] = a0;
            }
        }
        gsync(++ep);

        // ===== P3: gates GEMM, B resident in smem, A streamed ===============
        {
            wmma::fragment<wmma::accumulator, 16, 16, 8, float> acc[2];
            wmma::fill_fragment(acc[0], 0.0f);
            wmma::fill_fragment(acc[1], 0.0f);

            float4 ra[4];
            #pragma unroll
            for (int i = 0; i < 4; i++) {
                int idx = tid + i * 256, m = idx >> 4, k4 = (idx & 15) << 2;
                ra[i] = __ldcg((const float4*)(g_xcat + (size_t)m * XDIM + kb + k4));
            }

            int buf = 0;
            #pragma unroll 1
            for (int it = 0; it < 10; it++) {
                float* Ab = As + buf * (64 * 68);
                #pragma unroll
                for (int i = 0; i < 4; i++) {
                    int idx = tid + i * 256, m = idx >> 4, k4 = (idx & 15) << 2;
                    float* pa = Ab + m * 68 + k4;
                    pa[0] = tf32r(ra[i].x); pa[1] = tf32r(ra[i].y);
                    pa[2] = tf32r(ra[i].z); pa[3] = tf32r(ra[i].w);
                }
                __syncthreads();

                if (it < 9) {
                    const int kn = kb + (it + 1) * 64;
                    #pragma unroll
                    for (int i = 0; i < 4; i++) {
                        int idx = tid + i * 256, m = idx >> 4, k4 = (idx & 15) << 2;
                        ra[i] = __ldcg((const float4*)(g_xcat + (size_t)m * XDIM + kn + k4));
                    }
                }

                const int kloc = it * 64;
                #pragma unroll
                for (int kk = 0; kk < 64; kk += 8) {
                    wmma::fragment<wmma::matrix_a, 16, 16, 8, wmma::precision::tf32, wmma::row_major> af;
                    wmma::load_matrix_sync(af, Ab + m16 * 68 + kk, 68);
                    #pragma unroll
                    for (int j = 0; j < 2; j++) {
                        wmma::fragment<wmma::matrix_b, 16, 16, 8, wmma::precision::tf32, wmma::col_major> bf;
                        wmma::load_matrix_sync(bf, w_res + (size_t)(nb2 + j * 16) * 652 + kloc + kk, 652);
                        wmma::mma_sync(acc[j], af, bf, acc[j]);
                    }
                }
                buf ^= 1;
            }
            __syncthreads();
            wmma::store_matrix_sync(As + m16 * 68 + nb2,      acc[0], 68, wmma::mem_row_major);
            wmma::store_matrix_sync(As + m16 * 68 + nb2 + 16, acc[1], 68, wmma::mem_row_major);
            __syncthreads();
            float* gp = g_gpart + (size_t)kz * (N_B * GDIM);
            for (int idx = tid; idx < 4096; idx += 256) {
                int m = idx >> 6, n = idx & 63;
                gp[m * GDIM + n0 + n] = As[m * 68 + n];
            }
        }
        gsync(++ep);

        // ===== P4: LSTM pointwise (c held in register) ======================
        {
            float gi = g_bcat[ej];
            float gf = g_bcat[512 + ej];
            float gg = g_bcat[1024 + ej];
            float go = g_bcat[1536 + ej];
            #pragma unroll
            for (int z = 0; z < 4; z++) {
                const float* g = g_gpart + (size_t)z * (N_B * GDIM) + en * GDIM;
                gi += __ldcg(g + ej);
                gf += __ldcg(g + 512 + ej);
                gg += __ldcg(g + 1024 + ej);
                go += __ldcg(g + 1536 + ej);
            }
            float si = 1.0f / (1.0f + __expf(-gi));
            float sf = 1.0f / (1.0f + __expf(-gf));
            float so = 1.0f / (1.0f + __expf(-go));
            float cn = sf * creg + si * tanhf(gg);
            float hn = so * tanhf(cn);
            creg = cn;
            g_hall[((size_t)t * N_B + en) * H_H + ej] = hn;
            g_xcat[en * XDIM + HOFF + ej] = hn;
            if (t + 1 < T_T)
                g_xcat[en * XDIM + ENC_C + ej] = g_emb[((size_t)(t + 1) * N_B + en) * E_E + ej];
        }
        if (t + 1 < T_T) gsync(++ep);
    }
}

// ---------------- launch ----------------------------------------------------
extern "C" void kernel_launch(void* const* d_in, const int* in_sizes, int n_in,
                              void* d_out, int out_size)
{
    const float* features     = (const float*)d_in[0];
    const int*   captions     = (const int*)  d_in[1];
    const float* embd_W       = (const float*)d_in[2];
    const float* attn_token_W = (const float*)d_in[3];
    const float* attn_token_b = (const float*)d_in[4];
    const float* attn_feat_W  = (const float*)d_in[5];
    const float* attn_feat_b  = (const float*)d_in[6];
    const float* attn_full_W  = (const float*)d_in[7];
    const float* attn_full_b  = (const float*)d_in[8];
    const float* W_ih         = (const float*)d_in[9];
    const float* b_ih         = (const float*)d_in[10];
    const float* W_hh         = (const float*)d_in[11];
    const float* b_hh         = (const float*)d_in[12];
    const float* fc_W         = (const float*)d_in[13];
    const float* fc_b         = (const float*)d_in[14];
    const float* init_Wh      = (const float*)d_in[15];
    const float* init_Wc      = (const float*)d_in[16];
    float* out = (float*)d_out;

    float *p_attn_img, *p_xcat, *p_c, *p_hall;
    cudaGetSymbolAddress((void**)&p_attn_img, g_attn_img);
    cudaGetSymbolAddress((void**)&p_xcat,     g_xcat);
    cudaGetSymbolAddress((void**)&p_c,        g_cstate);
    cudaGetSymbolAddress((void**)&p_hall,     g_hall);

    const size_t dsm_bytes = DSM_FLOATS * sizeof(float);   // 214272
    cudaFuncSetAttribute(decode_loop, cudaFuncAttributeMaxDynamicSharedMemorySize,
                         (int)dsm_bytes);

    // prologue
    prep_kernel<<<T_T * N_B, 512>>>(embd_W, captions);
    wcat_kernel<<<(GDIM * XDIM + 1023) / 1024, 1024>>>(W_ih, b_ih, W_hh, b_hh);

    // [h0 | c0] = feat_flat @ [Wh | Wc]  (merged, split-K=96, atomic)
    gemm_init<<<dim3(8, 1, 96), 256>>>(
        features, PENC, init_Wh, init_Wc, H_H,
        p_xcat + HOFF, XDIM, p_c, H_H, PENC, 1024);

    // attn_img = features @ attn_feat_W^T + b   (4096 x 512, K=1536)
    gemm_big<64, 0><<<dim3(4, 64), 256>>>(
        features, ENC_C, attn_feat_W, ENC_C, attn_feat_b,
        p_attn_img, A_A, A_A, ENC_C);

    // full 32-step decode in one persistent kernel
    decode_loop<<<NBLK, 256, dsm_bytes>>>(features, attn_token_W, attn_token_b,
                                          attn_full_W, attn_full_b);

    // preds = h_all @ fc_W^T + fc_b, remapped to (N, T, V)
    gemm_big<128, 2><<<dim3((V_V + 127) / 128, 16), 256>>>(
        p_hall, H_H, fc_W, H_H, fc_b,
        out, V_V, V_V, H_H);
}